// round 1
// baseline (speedup 1.0000x reference)
#include <cuda_runtime.h>
#include <cuda_bf16.h>

#define BB 512
#define TT 512
#define LL 64

// scratch (device globals: allocation-free)
__device__ float g_E[LL * LL];     // exp(trans)
__device__ float g_res[BB];        // per-batch (normalizer - path_score)

__global__ void crf_prep_kernel(const float* __restrict__ trans) {
    int i = blockIdx.x * blockDim.x + threadIdx.x;
    if (i < LL * LL) g_E[i] = __expf(trans[i]);
}

__global__ void __launch_bounds__(64) crf_main_kernel(
    const float* __restrict__ emission,   // [B,T,L]
    const int*   __restrict__ target,     // [B,T]
    const float* __restrict__ mask,       // [B,T]
    const float* __restrict__ start_trans,// [L]
    const float* __restrict__ trans,      // [L,L]
    const float* __restrict__ end_trans)  // [L]
{
    __shared__ float sm_mask[TT];
    __shared__ float sm_p[LL];
    __shared__ float sm_red[2];
    __shared__ float sm_x[2];

    const int b    = blockIdx.x;
    const int j    = threadIdx.x;      // label index 0..63
    const int warp = j >> 5;
    const int lane = j & 31;

    const float* emb = emission + (size_t)b * TT * LL;
    const int*   tgt = target   + (size_t)b * TT;

    // stage mask row into shared
    for (int t = j; t < TT; t += 64) sm_mask[t] = mask[(size_t)b * TT + t];
    __syncthreads();

    // ---------------- path score: parallel reduction over t ----------------
    // path = ps0 + sum_{t>=1} m_t*(trans[tgt_{t-1},tgt_t] + em[t,tgt_t])
    //             + sum_{t>=1} e_t*end_trans[tgt_t]
    float pacc = 0.0f;
    for (int t = 1 + j; t < TT; t += 64) {
        int   tp = tgt[t - 1];
        int   tc = tgt[t];
        float m  = sm_mask[t];
        float nm = (t + 1 < TT) ? sm_mask[t + 1] : 0.0f;
        float e  = (m > nm) ? 1.0f : 0.0f;
        pacc += m * (trans[tp * LL + tc] + emb[(size_t)t * LL + tc])
              + e * end_trans[tc];
    }
    if (j == 0) {
        int t0 = tgt[0];
        pacc += start_trans[t0] + emb[t0];
    }
    #pragma unroll
    for (int o = 16; o; o >>= 1) pacc += __shfl_xor_sync(0xffffffffu, pacc, o);
    if (lane == 0) sm_x[warp] = pacc;
    __syncthreads();
    const float path_score = sm_x[0] + sm_x[1];
    __syncthreads();

    // ---------------- forward recursion (normalizer) ----------------
    // E column j in registers
    float Ecol[LL];
    #pragma unroll
    for (int i = 0; i < LL; i++) Ecol[i] = g_E[i * LL + j];

    const float et = end_trans[j];
    float s = start_trans[j] + emb[j];          // t = 0

    float em_next = emb[LL + j];                // prefetch t = 1
    for (int t = 1; t < TT; t++) {
        float em_cur = em_next;
        if (t + 1 < TT) em_next = emb[(size_t)(t + 1) * LL + j];

        // block max of s over the 64 labels
        float wm = s;
        #pragma unroll
        for (int o = 16; o; o >>= 1) wm = fmaxf(wm, __shfl_xor_sync(0xffffffffu, wm, o));
        if (lane == 0) sm_red[warp] = wm;
        __syncthreads();
        const float M = fmaxf(sm_red[0], sm_red[1]);

        sm_p[j] = __expf(s - M);
        __syncthreads();

        float a0 = 0.f, a1 = 0.f, a2 = 0.f, a3 = 0.f;
        #pragma unroll
        for (int i = 0; i < LL; i += 4) {
            a0 += sm_p[i + 0] * Ecol[i + 0];
            a1 += sm_p[i + 1] * Ecol[i + 1];
            a2 += sm_p[i + 2] * Ecol[i + 2];
            a3 += sm_p[i + 3] * Ecol[i + 3];
        }
        const float nxt = M + __logf((a0 + a1) + (a2 + a3)) + em_cur;

        const float m  = sm_mask[t];
        const float nm = (t + 1 < TT) ? sm_mask[t + 1] : 0.0f;
        const float e  = (m > nm) ? 1.0f : 0.0f;
        s = m * nxt + (1.0f - m) * s + e * et;
    }

    // normalizer = logsumexp_j(s)
    float wm = s;
    #pragma unroll
    for (int o = 16; o; o >>= 1) wm = fmaxf(wm, __shfl_xor_sync(0xffffffffu, wm, o));
    if (lane == 0) sm_red[warp] = wm;
    __syncthreads();
    const float M = fmaxf(sm_red[0], sm_red[1]);
    float pe = __expf(s - M);
    #pragma unroll
    for (int o = 16; o; o >>= 1) pe += __shfl_xor_sync(0xffffffffu, pe, o);
    if (lane == 0) sm_x[warp] = pe;
    __syncthreads();
    if (j == 0) {
        const float norm = M + __logf(sm_x[0] + sm_x[1]);
        g_res[b] = norm - path_score;
    }
}

// deterministic mean over the 512 per-batch results
__global__ void crf_reduce_kernel(float* __restrict__ out) {
    __shared__ float sm[512];
    int t = threadIdx.x;
    sm[t] = g_res[t];
    __syncthreads();
    #pragma unroll
    for (int stride = 256; stride > 0; stride >>= 1) {
        if (t < stride) sm[t] += sm[t + stride];
        __syncthreads();
    }
    if (t == 0) out[0] = sm[0] * (1.0f / BB);
}

extern "C" void kernel_launch(void* const* d_in, const int* in_sizes, int n_in,
                              void* d_out, int out_size) {
    const float* emission    = (const float*)d_in[0];
    const int*   target      = (const int*)  d_in[1];
    const float* mask        = (const float*)d_in[2];
    const float* start_trans = (const float*)d_in[3];
    const float* trans       = (const float*)d_in[4];
    const float* end_trans   = (const float*)d_in[5];
    float* out = (float*)d_out;

    crf_prep_kernel<<<16, 256>>>(trans);
    crf_main_kernel<<<BB, 64>>>(emission, target, mask, start_trans, trans, end_trans);
    crf_reduce_kernel<<<1, 512>>>(out);
}

// round 2
// speedup vs baseline: 1.6710x; 1.6710x over previous
#include <cuda_runtime.h>
#include <cuda_bf16.h>

#define BB 512
#define TT 512
#define LL 64

__device__ float g_res[BB];        // per-batch (normalizer - path_score)

__global__ void __launch_bounds__(64) crf_main_kernel(
    const float* __restrict__ emission,   // [B,T,L]
    const int*   __restrict__ target,     // [B,T]
    const float* __restrict__ mask,       // [B,T]
    const float* __restrict__ start_trans,// [L]
    const float* __restrict__ trans,      // [L,L]
    const float* __restrict__ end_trans)  // [L]
{
    __shared__ float sm_mask[TT];
    __shared__ float sm_p[2][LL];
    __shared__ float sm_s0[2];
    __shared__ float sm_red[2];
    __shared__ float sm_x[2];

    const int b    = blockIdx.x;
    const int j    = threadIdx.x;      // label index 0..63
    const int warp = j >> 5;
    const int lane = j & 31;

    const float* emb = emission + (size_t)b * TT * LL;
    const int*   tgt = target   + (size_t)b * TT;

    // stage mask row into shared
    for (int t = j; t < TT; t += 64) sm_mask[t] = mask[(size_t)b * TT + t];

    // E column j in registers: E[i][j] = exp(trans[i][j])
    float Ecol[LL];
    #pragma unroll
    for (int i = 0; i < LL; i++) Ecol[i] = __expf(trans[i * LL + j]);

    __syncthreads();

    // ---------------- path score: parallel reduction over t ----------------
    float pacc = 0.0f;
    for (int t = 1 + j; t < TT; t += 64) {
        int   tp = tgt[t - 1];
        int   tc = tgt[t];
        float m  = sm_mask[t];
        float nm = (t + 1 < TT) ? sm_mask[t + 1] : 0.0f;
        float e  = (m > nm) ? 1.0f : 0.0f;
        pacc += m * (trans[tp * LL + tc] + emb[(size_t)t * LL + tc])
              + e * end_trans[tc];
    }
    if (j == 0) {
        int t0 = tgt[0];
        pacc += start_trans[t0] + emb[t0];
    }
    #pragma unroll
    for (int o = 16; o; o >>= 1) pacc += __shfl_xor_sync(0xffffffffu, pacc, o);
    if (lane == 0) sm_x[warp] = pacc;
    __syncthreads();
    const float path_score = sm_x[0] + sm_x[1];

    // ---------------- forward recursion (normalizer) ----------------
    const float et = end_trans[j];
    float s = start_trans[j] + emb[j];          // t = 0

    // initial shift: thread 0's s at t=0 (block-uniform)
    if (j == 0) sm_s0[1] = s;
    __syncthreads();
    float S = sm_s0[1];

    float em_next = emb[LL + j];                // prefetch t = 1
    for (int t = 1; t < TT; t++) {
        const int buf = t & 1;
        const float em_cur = em_next;
        if (t + 1 < TT) em_next = emb[(size_t)(t + 1) * LL + j];

        // stabilized probs with block-uniform lagged shift S
        sm_p[buf][j] = __expf(s - S);
        if (j == 0) sm_s0[buf] = s;   // becomes next iteration's shift
        __syncthreads();

        // dot_j = sum_i p_i * E[i][j]   (vectorized broadcast reads)
        const float4* p4 = (const float4*)sm_p[buf];
        float a0 = 0.f, a1 = 0.f, a2 = 0.f, a3 = 0.f;
        #pragma unroll
        for (int i = 0; i < LL / 4; i++) {
            const float4 v = p4[i];
            a0 += v.x * Ecol[4 * i + 0];
            a1 += v.y * Ecol[4 * i + 1];
            a2 += v.z * Ecol[4 * i + 2];
            a3 += v.w * Ecol[4 * i + 3];
        }
        const float nxt = S + __logf((a0 + a1) + (a2 + a3)) + em_cur;

        const float m  = sm_mask[t];
        const float nm = (t + 1 < TT) ? sm_mask[t + 1] : 0.0f;
        const float e  = (m > nm) ? 1.0f : 0.0f;
        s = m * nxt + (1.0f - m) * s + e * et;

        S = sm_s0[buf];               // lag-1 shift for next iteration
    }

    // normalizer = logsumexp_j(s)  (exact max here; runs once)
    float wm = s;
    #pragma unroll
    for (int o = 16; o; o >>= 1) wm = fmaxf(wm, __shfl_xor_sync(0xffffffffu, wm, o));
    if (lane == 0) sm_red[warp] = wm;
    __syncthreads();
    const float M = fmaxf(sm_red[0], sm_red[1]);
    float pe = __expf(s - M);
    #pragma unroll
    for (int o = 16; o; o >>= 1) pe += __shfl_xor_sync(0xffffffffu, pe, o);
    if (lane == 0) sm_x[warp] = pe;
    __syncthreads();
    if (j == 0) {
        const float norm = M + __logf(sm_x[0] + sm_x[1]);
        g_res[b] = norm - path_score;
    }
}

// deterministic mean over the 512 per-batch results
__global__ void crf_reduce_kernel(float* __restrict__ out) {
    __shared__ float sm[512];
    int t = threadIdx.x;
    sm[t] = g_res[t];
    __syncthreads();
    #pragma unroll
    for (int stride = 256; stride > 0; stride >>= 1) {
        if (t < stride) sm[t] += sm[t + stride];
        __syncthreads();
    }
    if (t == 0) out[0] = sm[0] * (1.0f / BB);
}

extern "C" void kernel_launch(void* const* d_in, const int* in_sizes, int n_in,
                              void* d_out, int out_size) {
    const float* emission    = (const float*)d_in[0];
    const int*   target      = (const int*)  d_in[1];
    const float* mask        = (const float*)d_in[2];
    const float* start_trans = (const float*)d_in[3];
    const float* trans       = (const float*)d_in[4];
    const float* end_trans   = (const float*)d_in[5];
    float* out = (float*)d_out;

    crf_main_kernel<<<BB, 64>>>(emission, target, mask, start_trans, trans, end_trans);
    crf_reduce_kernel<<<1, 512>>>(out);
}